// round 1
// baseline (speedup 1.0000x reference)
#include <cuda_runtime.h>

#define TT   2048
#define HIDD 3584
#define NHQ  28
#define NKVH 4
#define HDIM 128
#define GQA  7
#define ASCALE 0.08838834764831845f   // 128^-0.5
#define LOG2_THETA 19.931568569324174f // log2(1e6)

// ---------------- scratch (static device globals; allocation-free) ----------
__device__ float g_q[(size_t)TT * HIDD];            // 2048 x 3584
__device__ float g_k[(size_t)TT * NKVH * HDIM];     // 2048 x 512
__device__ float g_v[(size_t)TT * NKVH * HDIM];     // 2048 x 512
__device__ float g_p[(size_t)NHQ * TT * TT];        // 28 x 2048 x 2048 scores/probs
__device__ float g_attn[(size_t)TT * HIDD];         // 2048 x 3584

// ---------------- generic tiled SGEMM: C = alpha * A @ op(B) + bias ---------
// BM=BN=128, BK=8, 256 threads, 8x8 microtile per thread.
// TRANSB=false: B is [K,N] row-major (ldb = row stride)
// TRANSB=true : B is [N,K] row-major, logical op(B)[k][n] = B[n*ldb + k]
// batching: A += z*aBatch ; B += (z/bDiv)*bBatch ; C += z*cBatch
template <bool TRANSB>
__global__ __launch_bounds__(256, 2)
void sgemm_kernel(const float* __restrict__ A, int lda, long aBatch,
                  const float* __restrict__ B, int ldb, long bBatch, int bDiv,
                  const float* __restrict__ bias,
                  float* __restrict__ C, int ldc, long cBatch,
                  int M, int N, int K, float alpha)
{
    __shared__ float As[8][128];   // As[k][m]
    __shared__ float Bs[8][128];   // Bs[k][n]

    const int z = blockIdx.z;
    A += (long)z * aBatch;
    B += (long)(z / bDiv) * bBatch;
    C += (long)z * cBatch;

    const int m0 = blockIdx.y * 128;
    const int n0 = blockIdx.x * 128;
    const int t  = threadIdx.x;

    // loader mapping (scatter-transpose style): 128 rows x 8 k, float4 along k
    const int lrow = t >> 1;
    const int lk   = (t & 1) * 4;
    // NN B loader mapping: 8 rows x 128 n, float4 along n
    const int brow = t >> 5;
    const int bcol = (t & 31) * 4;

    // compute mapping: 8x8 microtile
    const int tm = (t >> 4) * 8;
    const int tn = (t & 15) * 8;

    float acc[8][8];
#pragma unroll
    for (int i = 0; i < 8; i++)
#pragma unroll
        for (int j = 0; j < 8; j++) acc[i][j] = 0.0f;

    for (int k0 = 0; k0 < K; k0 += 8) {
        // ---- load A tile (transpose into As[k][m]) ----
        float4 av = *(const float4*)(A + (long)(m0 + lrow) * lda + (k0 + lk));
        As[lk + 0][lrow] = av.x;
        As[lk + 1][lrow] = av.y;
        As[lk + 2][lrow] = av.z;
        As[lk + 3][lrow] = av.w;

        // ---- load B tile ----
        if (TRANSB) {
            float4 bv = *(const float4*)(B + (long)(n0 + lrow) * ldb + (k0 + lk));
            Bs[lk + 0][lrow] = bv.x;
            Bs[lk + 1][lrow] = bv.y;
            Bs[lk + 2][lrow] = bv.z;
            Bs[lk + 3][lrow] = bv.w;
        } else {
            float4 bv = *(const float4*)(B + (long)(k0 + brow) * ldb + (n0 + bcol));
            *(float4*)&Bs[brow][bcol] = bv;
        }
        __syncthreads();

#pragma unroll
        for (int kk = 0; kk < 8; kk++) {
            float4 a0 = *(const float4*)&As[kk][tm];
            float4 a1 = *(const float4*)&As[kk][tm + 4];
            float4 b0 = *(const float4*)&Bs[kk][tn];
            float4 b1 = *(const float4*)&Bs[kk][tn + 4];
            float a[8] = {a0.x, a0.y, a0.z, a0.w, a1.x, a1.y, a1.z, a1.w};
            float b[8] = {b0.x, b0.y, b0.z, b0.w, b1.x, b1.y, b1.z, b1.w};
#pragma unroll
            for (int i = 0; i < 8; i++)
#pragma unroll
                for (int j = 0; j < 8; j++)
                    acc[i][j] = fmaf(a[i], b[j], acc[i][j]);
        }
        __syncthreads();
    }

    // ---- epilogue ----
#pragma unroll
    for (int i = 0; i < 8; i++) {
        long row = (long)(m0 + tm + i) * ldc;
        float4 o0, o1;
        o0.x = alpha * acc[i][0]; o0.y = alpha * acc[i][1];
        o0.z = alpha * acc[i][2]; o0.w = alpha * acc[i][3];
        o1.x = alpha * acc[i][4]; o1.y = alpha * acc[i][5];
        o1.z = alpha * acc[i][6]; o1.w = alpha * acc[i][7];
        if (bias != nullptr) {
            const float4 bb0 = *(const float4*)(bias + n0 + tn);
            const float4 bb1 = *(const float4*)(bias + n0 + tn + 4);
            o0.x += bb0.x; o0.y += bb0.y; o0.z += bb0.z; o0.w += bb0.w;
            o1.x += bb1.x; o1.y += bb1.y; o1.z += bb1.z; o1.w += bb1.w;
        }
        *(float4*)(C + row + n0 + tn)     = o0;
        *(float4*)(C + row + n0 + tn + 4) = o1;
    }
}

// ---------------- RoPE ------------------------------------------------------
// x: [T, nh, 128]; blockIdx = (t, head); 64 threads = half dim
__global__ void rope_kernel(float* __restrict__ x, const int* __restrict__ pos, int nh)
{
    const int t = blockIdx.x, h = blockIdx.y, d = threadIdx.x; // d in [0,64)
    float* row = x + ((long)t * nh + h) * HDIM;
    const float p = (float)pos[t];
    const float inv = exp2f(-(float)d * (LOG2_THETA / 64.0f));
    const float ang = p * inv;
    float s, c;
    sincosf(ang, &s, &c);
    const float x1 = row[d];
    const float x2 = row[d + 64];
    row[d]      = x1 * c - x2 * s;
    row[d + 64] = x2 * c + x1 * s;
}

// ---------------- row softmax (rows of length T) -----------------------------
__global__ void softmax_kernel(float* __restrict__ p)
{
    __shared__ float red[256];
    float* x = p + (long)blockIdx.x * TT;
    const int t = threadIdx.x;

    float m = -1e30f;
    for (int i = t; i < TT; i += 256) m = fmaxf(m, x[i]);
    red[t] = m; __syncthreads();
#pragma unroll
    for (int s = 128; s > 0; s >>= 1) {
        if (t < s) red[t] = fmaxf(red[t], red[t + s]);
        __syncthreads();
    }
    m = red[0];
    __syncthreads();

    float sum = 0.0f;
    for (int i = t; i < TT; i += 256) {
        float e = __expf(x[i] - m);
        x[i] = e;
        sum += e;
    }
    red[t] = sum; __syncthreads();
#pragma unroll
    for (int s = 128; s > 0; s >>= 1) {
        if (t < s) red[t] += red[t + s];
        __syncthreads();
    }
    const float inv = 1.0f / red[0];
    for (int i = t; i < TT; i += 256) x[i] *= inv;
}

// ---------------- launch -----------------------------------------------------
extern "C" void kernel_launch(void* const* d_in, const int* in_sizes, int n_in,
                              void* d_out, int out_size)
{
    const int*   pos = (const int*)d_in[0];
    const float* hs  = (const float*)d_in[1];
    const float* wq  = (const float*)d_in[2];
    const float* bq  = (const float*)d_in[3];
    const float* wk  = (const float*)d_in[4];
    const float* bk  = (const float*)d_in[5];
    const float* wv  = (const float*)d_in[6];
    const float* bv  = (const float*)d_in[7];
    const float* wo  = (const float*)d_in[8];
    float* out = (float*)d_out;

    float *q, *k, *v, *p, *attn;
    cudaGetSymbolAddress((void**)&q, g_q);
    cudaGetSymbolAddress((void**)&k, g_k);
    cudaGetSymbolAddress((void**)&v, g_v);
    cudaGetSymbolAddress((void**)&p, g_p);
    cudaGetSymbolAddress((void**)&attn, g_attn);

    // Q = hs @ wq + bq   (2048 x 3584, K=3584)
    sgemm_kernel<false><<<dim3(HIDD / 128, TT / 128, 1), 256>>>(
        hs, HIDD, 0, wq, HIDD, 0, 1, bq, q, HIDD, 0, TT, HIDD, HIDD, 1.0f);
    // K = hs @ wk + bk   (2048 x 512)
    sgemm_kernel<false><<<dim3(4, TT / 128, 1), 256>>>(
        hs, HIDD, 0, wk, NKVH * HDIM, 0, 1, bk, k, NKVH * HDIM, 0, TT, NKVH * HDIM, HIDD, 1.0f);
    // V = hs @ wv + bv   (2048 x 512)
    sgemm_kernel<false><<<dim3(4, TT / 128, 1), 256>>>(
        hs, HIDD, 0, wv, NKVH * HDIM, 0, 1, bv, v, NKVH * HDIM, 0, TT, NKVH * HDIM, HIDD, 1.0f);

    // RoPE on Q and K
    rope_kernel<<<dim3(TT, NHQ), 64>>>(q, pos, NHQ);
    rope_kernel<<<dim3(TT, NKVH), 64>>>(k, pos, NKVH);

    // scores[h] = Q_h @ K_{h/7}^T * SCALE   (2048 x 2048, K=128), batched over 28 heads
    sgemm_kernel<true><<<dim3(TT / 128, TT / 128, NHQ), 256>>>(
        q, HIDD, (long)HDIM,
        k, NKVH * HDIM, (long)HDIM, GQA,
        nullptr,
        p, TT, (long)TT * TT,
        TT, TT, HDIM, ASCALE);

    // softmax over each row
    softmax_kernel<<<NHQ * TT, 256>>>(p);

    // attn[h] = P_h @ V_{h/7}   (2048 x 128, K=2048)
    sgemm_kernel<false><<<dim3(1, TT / 128, NHQ), 256>>>(
        p, TT, (long)TT * TT,
        v, NKVH * HDIM, (long)HDIM, GQA,
        nullptr,
        attn, HIDD, (long)HDIM,
        TT, HDIM, TT, 1.0f);

    // out = attn @ wo   (2048 x 3584, K=3584)
    sgemm_kernel<false><<<dim3(HIDD / 128, TT / 128, 1), 256>>>(
        attn, HIDD, 0, wo, HIDD, 0, 1, nullptr, out, HIDD, 0, TT, HIDD, HIDD, 1.0f);
}

// round 3
// speedup vs baseline: 1.9417x; 1.9417x over previous
#include <cuda_runtime.h>
#include <cuda_bf16.h>
#include <cstdint>

#define TT    2048
#define HIDD  3584
#define NHQ   28
#define NKVH  4
#define HDIM  128
#define GQA   7
#define ASCALE 0.08838834764831845f    // 128^-0.5
#define LOG2_THETA 19.931568569324174f // log2(1e6)

// ------------------------- static device scratch ----------------------------
// split-bf16 layout: per row of logical K, store [hi(0..K-1) | lo(0..K-1)], ld = 2K
__device__ __nv_bfloat16 g_hsex [(size_t)TT * 2 * HIDD];
__device__ __nv_bfloat16 g_wqex [(size_t)HIDD * 2 * HIDD];
__device__ __nv_bfloat16 g_wkex [(size_t)(NKVH*HDIM) * 2 * HIDD];
__device__ __nv_bfloat16 g_wvex [(size_t)(NKVH*HDIM) * 2 * HIDD];
__device__ __nv_bfloat16 g_woex [(size_t)HIDD * 2 * HIDD];
__device__ float         g_q    [(size_t)TT * HIDD];
__device__ float         g_k    [(size_t)TT * NKVH * HDIM];
__device__ float         g_v    [(size_t)TT * NKVH * HDIM];
__device__ __nv_bfloat16 g_qex  [(size_t)NHQ * TT * 2 * HDIM];
__device__ __nv_bfloat16 g_kex  [(size_t)NKVH * TT * 2 * HDIM];
__device__ __nv_bfloat16 g_vex  [(size_t)NKVH * HDIM * 2 * TT];   // [4][128][4096] (V^T)
__device__ float         g_p    [(size_t)NHQ * TT * TT];
__device__ __nv_bfloat16 g_pex  [(size_t)NHQ * TT * 2 * TT];
__device__ float         g_attn [(size_t)TT * HIDD];
__device__ __nv_bfloat16 g_attnex[(size_t)TT * 2 * HIDD];

// ------------------------- helpers ------------------------------------------
__device__ __forceinline__ void split2(float x, __nv_bfloat16& h, __nv_bfloat16& l) {
    h = __float2bfloat16(x);
    l = __float2bfloat16(x - __bfloat162float(h));
}

__device__ __forceinline__ uint32_t smem_u32(const void* p) {
    uint32_t a;
    asm("{ .reg .u64 t; cvta.to.shared.u64 t, %1; cvt.u32.u64 %0, t; }" : "=r"(a) : "l"(p));
    return a;
}

__device__ __forceinline__ void cp16(uint32_t dst, const void* src) {
    asm volatile("cp.async.cg.shared.global [%0], [%1], 16;" :: "r"(dst), "l"(src));
}

// ------------------------- HMMA split-bf16 GEMM ------------------------------
// C[M,N] fp32 = alpha * (Ahi+Alo) @ (Bhi+Blo)^T + bias   (drop lo*lo term)
// A rows = M, B rows = N; both rows laid out [hi(Khalf) | lo(Khalf)].
// Tile 128x128, BK=32, 256 threads (8 warps, 2x4), K-loop = 3 regions x Khalf/32.
#define APAD 40                      // padded row stride (elems) -> conflict-free ldmatrix
#define TILE_ELEMS (128 * APAD)
#define TILE_BYTES (TILE_ELEMS * 2)

__global__ __launch_bounds__(256, 2) void mma_gemm(
    const __nv_bfloat16* __restrict__ A, long aBatch,
    const __nv_bfloat16* __restrict__ B, long bBatch, int bDiv,
    const float* __restrict__ bias,
    float* __restrict__ C, int ldc, long cBatch,
    int Khalf, float alpha)
{
    __shared__ __nv_bfloat16 As[2 * TILE_ELEMS];
    __shared__ __nv_bfloat16 Bs[2 * TILE_ELEMS];

    const int t   = threadIdx.x;
    const int wid = t >> 5, lid = t & 31;
    const int wm  = wid >> 2;          // 0..1  (64 rows)
    const int wn  = wid & 3;           // 0..3  (32 cols)
    const long lda = 2L * Khalf;
    const int m0 = blockIdx.y * 128, n0 = blockIdx.x * 128;

    A += (long)blockIdx.z * aBatch + (long)m0 * lda;
    B += (long)(blockIdx.z / bDiv) * bBatch + (long)n0 * lda;
    C += (long)blockIdx.z * cBatch;

    const uint32_t sA = smem_u32(As);
    const uint32_t sB = smem_u32(Bs);

    // loader mapping: 2 threads per row, each covers 32 bytes (2 x cp16)
    const int lr  = t >> 1;
    const int lc  = (t & 1) * 16;      // element col 0 or 16
    const uint32_t dA = sA + (lr * APAD + lc) * 2;
    const uint32_t dB = sB + (lr * APAD + lc) * 2;

    // ldmatrix per-lane offsets
    const int a_row = (lid & 7) + ((lid >> 3) & 1) * 8;   // 0..15
    const int a_c8  = (lid >> 4) * 8;                     // 0 or 8
    const int lb    = lid & 15;
    const int b_row = lb & 7;
    const int b_c8  = ((lb >> 3) & 1) * 8;
    const uint32_t aBase = sA + ((wm * 64 + a_row) * APAD + a_c8) * 2;
    const uint32_t bBase = sB + ((wn * 32 + b_row) * APAD + b_c8) * 2;

    const int nk   = Khalf >> 5;       // chunks per region
    const int nk3  = 3 * nk;

    float acc[4][4][4];
#pragma unroll
    for (int i = 0; i < 4; i++)
#pragma unroll
        for (int j = 0; j < 4; j++)
#pragma unroll
            for (int r = 0; r < 4; r++) acc[i][j][r] = 0.0f;

    // chunk c -> region r=c/nk, kk=c%nk; aoff/boff in elems
    auto issue = [&](int c) {
        int r  = c / nk;
        int kk = c - r * nk;
        long ao = (long)((r == 1) ? Khalf : 0) + kk * 32 + lc;
        long bo = (long)((r == 2) ? Khalf : 0) + kk * 32 + lc;
        uint32_t st = (uint32_t)(c & 1) * (uint32_t)TILE_BYTES;
        const __nv_bfloat16* ag = A + (long)lr * lda + ao;
        const __nv_bfloat16* bg = B + (long)lr * lda + bo;
        cp16(dA + st,      ag);
        cp16(dA + st + 16, ag + 8);
        cp16(dB + st,      bg);
        cp16(dB + st + 16, bg + 8);
    };

    issue(0);
    asm volatile("cp.async.commit_group;" ::: "memory");

    for (int c = 0; c < nk3; c++) {
        if (c + 1 < nk3) issue(c + 1);
        asm volatile("cp.async.commit_group;" ::: "memory");
        asm volatile("cp.async.wait_group 1;" ::: "memory");
        __syncthreads();

        const uint32_t st = (uint32_t)(c & 1) * (uint32_t)TILE_BYTES;
#pragma unroll
        for (int ks = 0; ks < 2; ks++) {
            uint32_t af[4][4], bf[4][2];
#pragma unroll
            for (int mi = 0; mi < 4; mi++) {
                uint32_t ad = aBase + st + (mi * 16 * APAD + ks * 16) * 2;
                asm volatile(
                    "ldmatrix.sync.aligned.m8n8.x4.shared.b16 {%0,%1,%2,%3}, [%4];"
                    : "=r"(af[mi][0]), "=r"(af[mi][1]), "=r"(af[mi][2]), "=r"(af[mi][3])
                    : "r"(ad));
            }
#pragma unroll
            for (int nj = 0; nj < 4; nj++) {
                uint32_t bd = bBase + st + (nj * 8 * APAD + ks * 16) * 2;
                asm volatile(
                    "ldmatrix.sync.aligned.m8n8.x2.shared.b16 {%0,%1}, [%2];"
                    : "=r"(bf[nj][0]), "=r"(bf[nj][1])
                    : "r"(bd));
            }
#pragma unroll
            for (int mi = 0; mi < 4; mi++)
#pragma unroll
                for (int nj = 0; nj < 4; nj++) {
                    asm volatile(
                        "mma.sync.aligned.m16n8k16.row.col.f32.bf16.bf16.f32 "
                        "{%0,%1,%2,%3}, {%4,%5,%6,%7}, {%8,%9}, {%0,%1,%2,%3};"
                        : "+f"(acc[mi][nj][0]), "+f"(acc[mi][nj][1]),
                          "+f"(acc[mi][nj][2]), "+f"(acc[mi][nj][3])
                        : "r"(af[mi][0]), "r"(af[mi][1]), "r"(af[mi][2]), "r"(af[mi][3]),
                          "r"(bf[nj][0]), "r"(bf[nj][1]));
                }
        }
        __syncthreads();
    }

    // epilogue: c0,c1 -> (row l/4, col (l%4)*2), c2,c3 -> row+8
    const int er = lid >> 2;
    const int ec = (lid & 3) * 2;
#pragma unroll
    for (int mi = 0; mi < 4; mi++) {
#pragma unroll
        for (int nj = 0; nj < 4; nj++) {
            int col = n0 + wn * 32 + nj * 8 + ec;
            float b0 = 0.f, b1 = 0.f;
            if (bias) { b0 = __ldg(bias + col); b1 = __ldg(bias + col + 1); }
            int row0 = m0 + wm * 64 + mi * 16 + er;
            float2 v0 = { alpha * acc[mi][nj][0] + b0, alpha * acc[mi][nj][1] + b1 };
            float2 v1 = { alpha * acc[mi][nj][2] + b0, alpha * acc[mi][nj][3] + b1 };
            *(float2*)(C + (long)row0 * ldc + col)       = v0;
            *(float2*)(C + (long)(row0 + 8) * ldc + col) = v1;
        }
    }
}

// ------------------------- conversion kernels -------------------------------
__global__ void split_rows(const float* __restrict__ in, __nv_bfloat16* __restrict__ out,
                           int K, long total4)
{
    long i = (long)blockIdx.x * blockDim.x + threadIdx.x;
    if (i >= total4) return;
    long e = i * 4;
    long r = e / K;
    int  k = (int)(e - r * K);
    float4 x = *(const float4*)(in + e);
    __nv_bfloat16 h0,l0,h1,l1,h2,l2,h3,l3;
    split2(x.x,h0,l0); split2(x.y,h1,l1); split2(x.z,h2,l2); split2(x.w,h3,l3);
    __nv_bfloat16* oh = out + r * 2L * K + k;
    oh[0]=h0; oh[1]=h1; oh[2]=h2; oh[3]=h3;
    __nv_bfloat16* ol = oh + K;
    ol[0]=l0; ol[1]=l1; ol[2]=l2; ol[3]=l3;
}

__global__ void split_transpose(const float* __restrict__ in, int ldin, long inBatch,
                                __nv_bfloat16* __restrict__ out, int Kdim, long outBatch)
{
    __shared__ float smt[32][33];
    const float* ip = in + (long)blockIdx.z * inBatch;
    __nv_bfloat16* op = out + (long)blockIdx.z * outBatch;
    int k0 = blockIdx.x * 32, n0 = blockIdx.y * 32;
    int tx = threadIdx.x, ty = threadIdx.y;
    for (int i = ty; i < 32; i += 8) smt[i][tx] = ip[(long)(k0 + i) * ldin + n0 + tx];
    __syncthreads();
    for (int j = ty; j < 32; j += 8) {
        float x = smt[tx][j];
        __nv_bfloat16 h, l; split2(x, h, l);
        long ob = (long)(n0 + j) * (2L * Kdim) + k0 + tx;
        op[ob] = h; op[ob + Kdim] = l;
    }
}

__global__ void rope_split(const float* __restrict__ x, const int* __restrict__ pos,
                           __nv_bfloat16* __restrict__ out, int nh)
{
    int t = blockIdx.x, h = blockIdx.y, d = threadIdx.x; // d in [0,64)
    const float* row = x + ((long)t * nh + h) * HDIM;
    float p = (float)pos[t];
    float ang = p * exp2f(-(float)d * (LOG2_THETA / 64.0f));
    float s, c;
    sincosf(ang, &s, &c);
    float x1 = row[d], x2 = row[d + 64];
    float y1 = x1 * c - x2 * s;
    float y2 = x2 * c + x1 * s;
    __nv_bfloat16 h1, l1, h2, l2;
    split2(y1, h1, l1); split2(y2, h2, l2);
    __nv_bfloat16* o = out + ((long)h * TT + t) * (2 * HDIM);
    o[d] = h1; o[d + 64] = h2;
    o[128 + d] = l1; o[128 + d + 64] = l2;
}

__global__ void softmax_split(const float* __restrict__ p, __nv_bfloat16* __restrict__ out)
{
    __shared__ float red[256];
    const float* x = p + (long)blockIdx.x * TT;
    __nv_bfloat16* o = out + (long)blockIdx.x * (2 * TT);
    const int t = threadIdx.x;

    float m = -1e30f;
    for (int i = t; i < TT; i += 256) m = fmaxf(m, x[i]);
    red[t] = m; __syncthreads();
#pragma unroll
    for (int s = 128; s > 0; s >>= 1) {
        if (t < s) red[t] = fmaxf(red[t], red[t + s]);
        __syncthreads();
    }
    m = red[0];
    __syncthreads();

    float sum = 0.0f;
    for (int i = t; i < TT; i += 256) sum += __expf(x[i] - m);
    red[t] = sum; __syncthreads();
#pragma unroll
    for (int s = 128; s > 0; s >>= 1) {
        if (t < s) red[t] += red[t + s];
        __syncthreads();
    }
    const float inv = 1.0f / red[0];

    for (int i = t; i < TT; i += 256) {
        float e = __expf(x[i] - m) * inv;
        __nv_bfloat16 h, l; split2(e, h, l);
        o[i] = h; o[TT + i] = l;
    }
}

// ------------------------- launch -------------------------------------------
extern "C" void kernel_launch(void* const* d_in, const int* in_sizes, int n_in,
                              void* d_out, int out_size)
{
    const int*   pos = (const int*)d_in[0];
    const float* hs  = (const float*)d_in[1];
    const float* wq  = (const float*)d_in[2];
    const float* bq  = (const float*)d_in[3];
    const float* wk  = (const float*)d_in[4];
    const float* bk  = (const float*)d_in[5];
    const float* wv  = (const float*)d_in[6];
    const float* bv  = (const float*)d_in[7];
    const float* wo  = (const float*)d_in[8];
    float* out = (float*)d_out;

    __nv_bfloat16 *hsex, *wqex, *wkex, *wvex, *woex, *qex, *kex, *vex, *pex, *attnex;
    float *q, *k, *v, *p, *attn;
    cudaGetSymbolAddress((void**)&hsex, g_hsex);
    cudaGetSymbolAddress((void**)&wqex, g_wqex);
    cudaGetSymbolAddress((void**)&wkex, g_wkex);
    cudaGetSymbolAddress((void**)&wvex, g_wvex);
    cudaGetSymbolAddress((void**)&woex, g_woex);
    cudaGetSymbolAddress((void**)&qex,  g_qex);
    cudaGetSymbolAddress((void**)&kex,  g_kex);
    cudaGetSymbolAddress((void**)&vex,  g_vex);
    cudaGetSymbolAddress((void**)&pex,  g_pex);
    cudaGetSymbolAddress((void**)&attnex, g_attnex);
    cudaGetSymbolAddress((void**)&q, g_q);
    cudaGetSymbolAddress((void**)&k, g_k);
    cudaGetSymbolAddress((void**)&v, g_v);
    cudaGetSymbolAddress((void**)&p, g_p);
    cudaGetSymbolAddress((void**)&attn, g_attn);

    // ---- operand conversions (hi/lo split) ----
    {
        long t4 = (long)TT * HIDD / 4;
        split_rows<<<(unsigned)((t4 + 255) / 256), 256>>>(hs, hsex, HIDD, t4);
    }
    split_transpose<<<dim3(HIDD/32, HIDD/32, 1), dim3(32,8)>>>(wq, HIDD, 0, wqex, HIDD, 0);
    split_transpose<<<dim3(HIDD/32, (NKVH*HDIM)/32, 1), dim3(32,8)>>>(wk, NKVH*HDIM, 0, wkex, HIDD, 0);
    split_transpose<<<dim3(HIDD/32, (NKVH*HDIM)/32, 1), dim3(32,8)>>>(wv, NKVH*HDIM, 0, wvex, HIDD, 0);
    split_transpose<<<dim3(HIDD/32, HIDD/32, 1), dim3(32,8)>>>(wo, HIDD, 0, woex, HIDD, 0);

    // ---- QKV projections ----
    mma_gemm<<<dim3(HIDD/128, TT/128, 1), 256>>>(
        hsex, 0, wqex, 0, 1, bq, q, HIDD, 0, HIDD, 1.0f);
    mma_gemm<<<dim3((NKVH*HDIM)/128, TT/128, 1), 256>>>(
        hsex, 0, wkex, 0, 1, bk, k, NKVH*HDIM, 0, HIDD, 1.0f);
    mma_gemm<<<dim3((NKVH*HDIM)/128, TT/128, 1), 256>>>(
        hsex, 0, wvex, 0, 1, bv, v, NKVH*HDIM, 0, HIDD, 1.0f);

    // ---- RoPE + split; V transpose + split ----
    rope_split<<<dim3(TT, NHQ), 64>>>(q, pos, qex, NHQ);
    rope_split<<<dim3(TT, NKVH), 64>>>(k, pos, kex, NKVH);
    split_transpose<<<dim3(TT/32, HDIM/32, NKVH), dim3(32,8)>>>(
        v, NKVH*HDIM, (long)HDIM, vex, TT, (long)HDIM * 2 * TT);

    // ---- scores = Q @ K^T * scale ----
    mma_gemm<<<dim3(TT/128, TT/128, NHQ), 256>>>(
        qex, (long)TT * 2 * HDIM,
        kex, (long)TT * 2 * HDIM, GQA,
        nullptr, p, TT, (long)TT * TT,
        HDIM, ASCALE);

    // ---- softmax + split ----
    softmax_split<<<NHQ * TT, 256>>>(p, pex);

    // ---- attn = P @ V ----
    mma_gemm<<<dim3(1, TT/128, NHQ), 256>>>(
        pex, (long)TT * 2 * TT,
        vex, (long)HDIM * 2 * TT, GQA,
        nullptr, attn, HIDD, (long)HDIM,
        TT, 1.0f);

    // ---- out = attn @ wo ----
    {
        long t4 = (long)TT * HIDD / 4;
        split_rows<<<(unsigned)((t4 + 255) / 256), 256>>>(attn, attnex, HIDD, t4);
    }
    mma_gemm<<<dim3(HIDD/128, TT/128, 1), 256>>>(
        attnex, 0, woex, 0, 1, nullptr, out, HIDD, 0, HIDD, 1.0f);
}

// round 4
// speedup vs baseline: 3.0509x; 1.5712x over previous
#include <cuda_runtime.h>
#include <cuda_bf16.h>
#include <cstdint>

#define TT    2048
#define HIDD  3584
#define NHQ   28
#define NKVH  4
#define HDIM  128
#define GQA   7
#define NQKV  4608                     // 3584 + 512 + 512
#define ASCALE 0.08838834764831845f    // 128^-0.5
#define LOG2_THETA 19.931568569324174f // log2(1e6)

// ------------------------- static device scratch ----------------------------
__device__ __nv_bfloat16 g_hsex  [(size_t)TT * 2 * HIDD];
__device__ __nv_bfloat16 g_wqkvex[(size_t)NQKV * 2 * HIDD];       // [4608][7168]
__device__ float         g_bqkv  [NQKV];
__device__ __nv_bfloat16 g_woex  [(size_t)HIDD * 2 * HIDD];
__device__ float         g_qkv   [(size_t)TT * NQKV];             // [2048][4608]
__device__ __nv_bfloat16 g_qex   [(size_t)NHQ * TT * 2 * HDIM];
__device__ __nv_bfloat16 g_kex   [(size_t)NKVH * TT * 2 * HDIM];
__device__ __nv_bfloat16 g_vex   [(size_t)NKVH * HDIM * 2 * TT];  // [4][128][4096] (V^T)
__device__ float         g_p     [(size_t)NHQ * TT * TT];
__device__ __nv_bfloat16 g_pex   [(size_t)NHQ * TT * 2 * TT];
__device__ float         g_attn  [(size_t)TT * HIDD];
__device__ __nv_bfloat16 g_attnex[(size_t)TT * 2 * HIDD];

// ------------------------- helpers ------------------------------------------
__device__ __forceinline__ void split2(float x, __nv_bfloat16& h, __nv_bfloat16& l) {
    h = __float2bfloat16(x);
    l = __float2bfloat16(x - __bfloat162float(h));
}

__device__ __forceinline__ uint32_t smem_u32(const void* p) {
    uint32_t a;
    asm("{ .reg .u64 t; cvta.to.shared.u64 t, %1; cvt.u32.u64 %0, t; }" : "=r"(a) : "l"(p));
    return a;
}

__device__ __forceinline__ void cp16(uint32_t dst, const void* src) {
    asm volatile("cp.async.cg.shared.global [%0], [%1], 16;" :: "r"(dst), "l"(src));
}

// ------------------------- HMMA split-bf16 GEMM ------------------------------
// C[M,N] fp32 = alpha * (Ahi+Alo) @ (Bhi+Blo)^T + bias  (lo*lo dropped)
// Rows of A/B laid out [hi(Khalf) | lo(Khalf)]. Tile BMx128, BK=32, 256 thr,
// 4-stage cp.async pipeline. K-loop = 3 regions x (Khalf/32).
#define APAD   40
#define STAGES 4

template <int BM>
__global__ __launch_bounds__(256, BM == 128 ? 2 : 3) void mma_gemm(
    const __nv_bfloat16* __restrict__ A, long aBatch,
    const __nv_bfloat16* __restrict__ B, long bBatch, int bDiv,
    const float* __restrict__ bias,
    float* __restrict__ C, int ldc, long cBatch,
    int Khalf, float alpha)
{
    constexpr int MI     = BM / 32;             // 16-row frags per warp
    constexpr int ACP    = BM / 64;             // cp16 per thread for A tile
    constexpr int ABYTES = BM * APAD * 2;
    constexpr int BBYTES = 128 * APAD * 2;

    extern __shared__ char sm[];
    const uint32_t sA = smem_u32(sm);
    const uint32_t sB = sA + STAGES * ABYTES;

    const int t   = threadIdx.x;
    const int wid = t >> 5, lid = t & 31;
    const int wm  = wid >> 2;                   // 0..1
    const int wn  = wid & 3;                    // 0..3
    const long lda = 2L * Khalf;
    const int m0 = blockIdx.y * BM, n0 = blockIdx.x * 128;

    A += (long)blockIdx.z * aBatch + (long)m0 * lda;
    B += (long)(blockIdx.z / bDiv) * bBatch + (long)n0 * lda;
    C += (long)blockIdx.z * cBatch;

    // ldmatrix per-lane offsets
    const int a_row = (lid & 7) + ((lid >> 3) & 1) * 8;
    const int a_c8  = (lid >> 4) * 8;
    const int lb    = lid & 15;
    const int b_row = lb & 7;
    const int b_c8  = ((lb >> 3) & 1) * 8;
    const uint32_t aBase = sA + ((wm * (BM / 2) + a_row) * APAD + a_c8) * 2;
    const uint32_t bBase = sB + ((wn * 32 + b_row) * APAD + b_c8) * 2;

    const int nk  = Khalf >> 5;
    const int nk3 = 3 * nk;

    float acc[MI][4][4];
#pragma unroll
    for (int i = 0; i < MI; i++)
#pragma unroll
        for (int j = 0; j < 4; j++)
#pragma unroll
            for (int r = 0; r < 4; r++) acc[i][j][r] = 0.0f;

    auto issue = [&](int c) {
        int r  = c / nk;
        int kk = c - r * nk;
        long ao = (long)((r == 1) ? Khalf : 0) + (long)kk * 32;
        long bo = (long)((r == 2) ? Khalf : 0) + (long)kk * 32;
        uint32_t stA = (uint32_t)(c & (STAGES - 1)) * ABYTES;
        uint32_t stB = (uint32_t)(c & (STAGES - 1)) * BBYTES;
#pragma unroll
        for (int i = 0; i < ACP; i++) {
            int idx = t + i * 256, row = idx >> 2, q = (idx & 3) * 8;
            cp16(sA + stA + (row * APAD + q) * 2, A + (long)row * lda + ao + q);
        }
#pragma unroll
        for (int i = 0; i < 2; i++) {
            int idx = t + i * 256, row = idx >> 2, q = (idx & 3) * 8;
            cp16(sB + stB + (row * APAD + q) * 2, B + (long)row * lda + bo + q);
        }
    };

#pragma unroll
    for (int s = 0; s < STAGES - 1; s++) {
        issue(s);
        asm volatile("cp.async.commit_group;" ::: "memory");
    }

    for (int c = 0; c < nk3; c++) {
        asm volatile("cp.async.wait_group %0;" :: "n"(STAGES - 2) : "memory");
        __syncthreads();

        const uint32_t stA = (uint32_t)(c & (STAGES - 1)) * ABYTES;
        const uint32_t stB = (uint32_t)(c & (STAGES - 1)) * BBYTES;
#pragma unroll
        for (int ks = 0; ks < 2; ks++) {
            uint32_t af[MI][4], bf[4][2];
#pragma unroll
            for (int mi = 0; mi < MI; mi++) {
                uint32_t ad = aBase + stA + (mi * 16 * APAD + ks * 16) * 2;
                asm volatile(
                    "ldmatrix.sync.aligned.m8n8.x4.shared.b16 {%0,%1,%2,%3}, [%4];"
                    : "=r"(af[mi][0]), "=r"(af[mi][1]), "=r"(af[mi][2]), "=r"(af[mi][3])
                    : "r"(ad));
            }
#pragma unroll
            for (int nj = 0; nj < 4; nj++) {
                uint32_t bd = bBase + stB + (nj * 8 * APAD + ks * 16) * 2;
                asm volatile(
                    "ldmatrix.sync.aligned.m8n8.x2.shared.b16 {%0,%1}, [%2];"
                    : "=r"(bf[nj][0]), "=r"(bf[nj][1])
                    : "r"(bd));
            }
#pragma unroll
            for (int mi = 0; mi < MI; mi++)
#pragma unroll
                for (int nj = 0; nj < 4; nj++) {
                    asm volatile(
                        "mma.sync.aligned.m16n8k16.row.col.f32.bf16.bf16.f32 "
                        "{%0,%1,%2,%3}, {%4,%5,%6,%7}, {%8,%9}, {%0,%1,%2,%3};"
                        : "+f"(acc[mi][nj][0]), "+f"(acc[mi][nj][1]),
                          "+f"(acc[mi][nj][2]), "+f"(acc[mi][nj][3])
                        : "r"(af[mi][0]), "r"(af[mi][1]), "r"(af[mi][2]), "r"(af[mi][3]),
                          "r"(bf[nj][0]), "r"(bf[nj][1]));
                }
        }
        if (c + STAGES - 1 < nk3) issue(c + STAGES - 1);
        asm volatile("cp.async.commit_group;" ::: "memory");
    }

    // epilogue
    const int er = lid >> 2;
    const int ec = (lid & 3) * 2;
#pragma unroll
    for (int nj = 0; nj < 4; nj++) {
        int col = n0 + wn * 32 + nj * 8 + ec;
        float b0 = 0.f, b1 = 0.f;
        if (bias) { b0 = __ldg(bias + col); b1 = __ldg(bias + col + 1); }
#pragma unroll
        for (int mi = 0; mi < MI; mi++) {
            int row0 = m0 + wm * (BM / 2) + mi * 16 + er;
            float2 v0 = { alpha * acc[mi][nj][0] + b0, alpha * acc[mi][nj][1] + b1 };
            float2 v1 = { alpha * acc[mi][nj][2] + b0, alpha * acc[mi][nj][3] + b1 };
            *(float2*)(C + (long)row0 * ldc + col)       = v0;
            *(float2*)(C + (long)(row0 + 8) * ldc + col) = v1;
        }
    }
}

// ------------------------- conversion kernels -------------------------------
__global__ void split_rows(const float* __restrict__ in, __nv_bfloat16* __restrict__ out,
                           int K, long total4)
{
    long i = (long)blockIdx.x * blockDim.x + threadIdx.x;
    if (i >= total4) return;
    long e = i * 4;
    long r = e / K;
    int  k = (int)(e - r * K);
    float4 x = *(const float4*)(in + e);
    __nv_bfloat16 h0,l0,h1,l1,h2,l2,h3,l3;
    split2(x.x,h0,l0); split2(x.y,h1,l1); split2(x.z,h2,l2); split2(x.w,h3,l3);
    __nv_bfloat16* oh = out + r * 2L * K + k;
    oh[0]=h0; oh[1]=h1; oh[2]=h2; oh[3]=h3;
    __nv_bfloat16* ol = oh + K;
    ol[0]=l0; ol[1]=l1; ol[2]=l2; ol[3]=l3;
}

// in: logical [Kdim rows x N cols] (row stride ldin, batch stride inBatch)
// out: bf16 [N rows][2*Kdim] (batch stride outBatch)
__global__ void split_transpose(const float* __restrict__ in, int ldin, long inBatch,
                                __nv_bfloat16* __restrict__ out, int Kdim, long outBatch)
{
    __shared__ float smt[32][33];
    const float* ip = in + (long)blockIdx.z * inBatch;
    __nv_bfloat16* op = out + (long)blockIdx.z * outBatch;
    int k0 = blockIdx.x * 32, n0 = blockIdx.y * 32;
    int tx = threadIdx.x, ty = threadIdx.y;
    for (int i = ty; i < 32; i += 8) smt[i][tx] = ip[(long)(k0 + i) * ldin + n0 + tx];
    __syncthreads();
    for (int j = ty; j < 32; j += 8) {
        float x = smt[tx][j];
        __nv_bfloat16 h, l; split2(x, h, l);
        long ob = (long)(n0 + j) * (2L * Kdim) + k0 + tx;
        op[ob] = h; op[ob + Kdim] = l;
    }
}

// RoPE + split: x fp32 rows at x[t*ld + h*128 + d] -> out bf16 [nh][T][256]
__global__ void rope_split(const float* __restrict__ x, int ld, const int* __restrict__ pos,
                           __nv_bfloat16* __restrict__ out)
{
    int t = blockIdx.x, h = blockIdx.y, d = threadIdx.x; // d in [0,64)
    const float* row = x + (long)t * ld + h * HDIM;
    float p = (float)pos[t];
    float ang = p * exp2f(-(float)d * (LOG2_THETA / 64.0f));
    float s, c;
    sincosf(ang, &s, &c);
    float x1 = row[d], x2 = row[d + 64];
    float y1 = x1 * c - x2 * s;
    float y2 = x2 * c + x1 * s;
    __nv_bfloat16 h1, l1, h2, l2;
    split2(y1, h1, l1); split2(y2, h2, l2);
    __nv_bfloat16* o = out + ((long)h * TT + t) * (2 * HDIM);
    o[d] = h1; o[d + 64] = h2;
    o[128 + d] = l1; o[128 + d + 64] = l2;
}

// single-pass softmax: row cached in 8 regs/thread
__global__ void softmax_fused(const float* __restrict__ p, __nv_bfloat16* __restrict__ out)
{
    __shared__ float red[256];
    const float* xr = p + (long)blockIdx.x * TT;
    __nv_bfloat16* o = out + (long)blockIdx.x * (2 * TT);
    const int t = threadIdx.x;

    float x[8];
    float m = -1e30f;
#pragma unroll
    for (int j = 0; j < 8; j++) { x[j] = xr[t + j * 256]; m = fmaxf(m, x[j]); }
    red[t] = m; __syncthreads();
#pragma unroll
    for (int s = 128; s > 0; s >>= 1) {
        if (t < s) red[t] = fmaxf(red[t], red[t + s]);
        __syncthreads();
    }
    m = red[0];
    __syncthreads();

    float sum = 0.0f;
#pragma unroll
    for (int j = 0; j < 8; j++) { x[j] = __expf(x[j] - m); sum += x[j]; }
    red[t] = sum; __syncthreads();
#pragma unroll
    for (int s = 128; s > 0; s >>= 1) {
        if (t < s) red[t] += red[t + s];
        __syncthreads();
    }
    const float inv = 1.0f / red[0];
#pragma unroll
    for (int j = 0; j < 8; j++) {
        float e = x[j] * inv;
        __nv_bfloat16 h, l; split2(e, h, l);
        int i = t + j * 256;
        o[i] = h; o[TT + i] = l;
    }
}

__global__ void concat_bias(const float* __restrict__ bq, const float* __restrict__ bk,
                            const float* __restrict__ bv, float* __restrict__ o)
{
    int i = blockIdx.x * 256 + threadIdx.x;
    if (i >= NQKV) return;
    if (i < HIDD)            o[i] = bq[i];
    else if (i < HIDD + 512) o[i] = bk[i - HIDD];
    else                     o[i] = bv[i - HIDD - 512];
}

// ------------------------- launch -------------------------------------------
extern "C" void kernel_launch(void* const* d_in, const int* in_sizes, int n_in,
                              void* d_out, int out_size)
{
    const int*   pos = (const int*)d_in[0];
    const float* hs  = (const float*)d_in[1];
    const float* wq  = (const float*)d_in[2];
    const float* bq  = (const float*)d_in[3];
    const float* wk  = (const float*)d_in[4];
    const float* bk  = (const float*)d_in[5];
    const float* wv  = (const float*)d_in[6];
    const float* bv  = (const float*)d_in[7];
    const float* wo  = (const float*)d_in[8];
    float* out = (float*)d_out;

    __nv_bfloat16 *hsex, *wqkvex, *woex, *qex, *kex, *vex, *pex, *attnex;
    float *qkv, *p, *attn, *bqkv;
    cudaGetSymbolAddress((void**)&hsex,   g_hsex);
    cudaGetSymbolAddress((void**)&wqkvex, g_wqkvex);
    cudaGetSymbolAddress((void**)&bqkv,   g_bqkv);
    cudaGetSymbolAddress((void**)&woex,   g_woex);
    cudaGetSymbolAddress((void**)&qkv,    g_qkv);
    cudaGetSymbolAddress((void**)&qex,    g_qex);
    cudaGetSymbolAddress((void**)&kex,    g_kex);
    cudaGetSymbolAddress((void**)&vex,    g_vex);
    cudaGetSymbolAddress((void**)&pex,    g_pex);
    cudaGetSymbolAddress((void**)&attnex, g_attnex);
    cudaGetSymbolAddress((void**)&p,      g_p);
    cudaGetSymbolAddress((void**)&attn,   g_attn);

    static bool attrDone = false;
    if (!attrDone) {
        cudaFuncSetAttribute(mma_gemm<128>, cudaFuncAttributeMaxDynamicSharedMemorySize,
                             STAGES * (128 + 128) * APAD * 2);
        cudaFuncSetAttribute(mma_gemm<64>, cudaFuncAttributeMaxDynamicSharedMemorySize,
                             STAGES * (64 + 128) * APAD * 2);
        attrDone = true;
    }
    const int smem128 = STAGES * (128 + 128) * APAD * 2;
    const int smem64  = STAGES * (64 + 128) * APAD * 2;

    // ---- operand conversions ----
    {
        long t4 = (long)TT * HIDD / 4;
        split_rows<<<(unsigned)((t4 + 255) / 256), 256>>>(hs, hsex, HIDD, t4);
    }
    split_transpose<<<dim3(HIDD/32, HIDD/32, 1), dim3(32,8)>>>(wq, HIDD, 0, wqkvex, HIDD, 0);
    split_transpose<<<dim3(HIDD/32, 512/32, 1), dim3(32,8)>>>(wk, 512, 0,
        wqkvex + (size_t)HIDD * 2 * HIDD, HIDD, 0);
    split_transpose<<<dim3(HIDD/32, 512/32, 1), dim3(32,8)>>>(wv, 512, 0,
        wqkvex + (size_t)(HIDD + 512) * 2 * HIDD, HIDD, 0);
    split_transpose<<<dim3(HIDD/32, HIDD/32, 1), dim3(32,8)>>>(wo, HIDD, 0, woex, HIDD, 0);
    concat_bias<<<(NQKV + 255) / 256, 256>>>(bq, bk, bv, bqkv);

    // ---- fused QKV projection ----
    mma_gemm<128><<<dim3(NQKV/128, TT/128, 1), 256, smem128>>>(
        hsex, 0, wqkvex, 0, 1, bqkv, qkv, NQKV, 0, HIDD, 1.0f);

    // ---- RoPE + split; V transpose + split ----
    rope_split<<<dim3(TT, NHQ), 64>>>(qkv, NQKV, pos, qex);
    rope_split<<<dim3(TT, NKVH), 64>>>(qkv + HIDD, NQKV, pos, kex);
    split_transpose<<<dim3(TT/32, HDIM/32, NKVH), dim3(32,8)>>>(
        qkv + HIDD + 512, NQKV, (long)HDIM, vex, TT, (long)HDIM * 2 * TT);

    // ---- scores = Q @ K^T * scale ----
    mma_gemm<128><<<dim3(TT/128, TT/128, NHQ), 256, smem128>>>(
        qex, (long)TT * 2 * HDIM,
        kex, (long)TT * 2 * HDIM, GQA,
        nullptr, p, TT, (long)TT * TT,
        HDIM, ASCALE);

    // ---- softmax (single pass) ----
    softmax_fused<<<NHQ * TT, 256>>>(p, pex);

    // ---- attn = P @ V  (BM=64 for wave efficiency) ----
    mma_gemm<64><<<dim3(1, TT/64, NHQ), 256, smem64>>>(
        pex, (long)TT * 2 * TT,
        vex, (long)HDIM * 2 * TT, GQA,
        nullptr, attn, HIDD, (long)HDIM,
        TT, 1.0f);

    // ---- out = attn @ wo ----
    {
        long t4 = (long)TT * HIDD / 4;
        split_rows<<<(unsigned)((t4 + 255) / 256), 256>>>(attn, attnex, HIDD, t4);
    }
    mma_gemm<128><<<dim3(HIDD/128, TT/128, 1), 256, smem128>>>(
        attnex, 0, woex, 0, 1, nullptr, out, HIDD, 0, HIDD, 1.0f);
}

// round 5
// speedup vs baseline: 3.7397x; 1.2258x over previous
#include <cuda_runtime.h>
#include <cuda_bf16.h>
#include <cstdint>

#define TT    2048
#define HIDD  3584
#define NHQ   28
#define NKVH  4
#define HDIM  128
#define GQA   7
#define NQKV  4608
#define ASCALE 0.08838834764831845f
#define SCALE_L2E 0.12751743f          // ASCALE * log2(e)
#define LOG2_THETA 19.931568569324174f

// ------------------------- static device scratch ----------------------------
__device__ __nv_bfloat16 g_hsex  [(size_t)TT * 2 * HIDD];
__device__ __nv_bfloat16 g_wqkvex[(size_t)NQKV * 2 * HIDD];
__device__ float         g_bqkv  [NQKV];
__device__ __nv_bfloat16 g_woex  [(size_t)HIDD * 2 * HIDD];
__device__ float         g_qkv   [(size_t)TT * NQKV];
__device__ __nv_bfloat16 g_qex   [(size_t)NHQ * TT * 2 * HDIM];
__device__ __nv_bfloat16 g_kex   [(size_t)NKVH * TT * 2 * HDIM];
__device__ __nv_bfloat16 g_vex   [(size_t)NKVH * HDIM * 2 * TT];  // V^T [4][128][hi(2048)|lo(2048)]
__device__ __nv_bfloat16 g_attnex[(size_t)TT * 2 * HIDD];

// ------------------------- helpers ------------------------------------------
__device__ __forceinline__ void split2(float x, __nv_bfloat16& h, __nv_bfloat16& l) {
    h = __float2bfloat16(x);
    l = __float2bfloat16(x - __bfloat162float(h));
}

__device__ __forceinline__ uint32_t smem_u32(const void* p) {
    uint32_t a;
    asm("{ .reg .u64 t; cvta.to.shared.u64 t, %1; cvt.u32.u64 %0, t; }" : "=r"(a) : "l"(p));
    return a;
}

__device__ __forceinline__ void cp16(uint32_t dst, const void* src) {
    asm volatile("cp.async.cg.shared.global [%0], [%1], 16;" :: "r"(dst), "l"(src));
}

__device__ __forceinline__ void hmma(float* c, const uint32_t* a, const uint32_t* b) {
    asm volatile(
        "mma.sync.aligned.m16n8k16.row.col.f32.bf16.bf16.f32 "
        "{%0,%1,%2,%3}, {%4,%5,%6,%7}, {%8,%9}, {%0,%1,%2,%3};"
        : "+f"(c[0]), "+f"(c[1]), "+f"(c[2]), "+f"(c[3])
        : "r"(a[0]), "r"(a[1]), "r"(a[2]), "r"(a[3]), "r"(b[0]), "r"(b[1]));
}

__device__ __forceinline__ void ldx4(uint32_t* r, uint32_t addr) {
    asm volatile("ldmatrix.sync.aligned.m8n8.x4.shared.b16 {%0,%1,%2,%3}, [%4];"
                 : "=r"(r[0]), "=r"(r[1]), "=r"(r[2]), "=r"(r[3]) : "r"(addr));
}

__device__ __forceinline__ void ldx2(uint32_t* r, uint32_t addr) {
    asm volatile("ldmatrix.sync.aligned.m8n8.x2.shared.b16 {%0,%1}, [%2];"
                 : "=r"(r[0]), "=r"(r[1]) : "r"(addr));
}

__device__ __forceinline__ uint32_t packbf(float a, float b) {
    __nv_bfloat162 v = __floats2bfloat162_rn(a, b);
    return *reinterpret_cast<uint32_t*>(&v);
}

__device__ __forceinline__ void packsplit(float a, float b, uint32_t& hi, uint32_t& lo) {
    __nv_bfloat16 ha = __float2bfloat16(a), hb = __float2bfloat16(b);
    float la = a - __bfloat162float(ha);
    float lb = b - __bfloat162float(hb);
    __nv_bfloat162 hv; hv.x = ha; hv.y = hb;
    hi = *reinterpret_cast<uint32_t*>(&hv);
    lo = packbf(la, lb);
}

// ------------------------- HMMA split-bf16 GEMM (projections) ----------------
#define APAD   40
#define STAGES 4

template <int BM>
__global__ __launch_bounds__(256, 2) void mma_gemm(
    const __nv_bfloat16* __restrict__ A,
    const __nv_bfloat16* __restrict__ B,
    const float* __restrict__ bias,
    float* __restrict__ C, int ldc,
    int Khalf, float alpha)
{
    constexpr int MI     = BM / 32;
    constexpr int ACP    = BM / 64;
    constexpr int ABYTES = BM * APAD * 2;
    constexpr int BBYTES = 128 * APAD * 2;

    extern __shared__ char sm[];
    const uint32_t sA = smem_u32(sm);
    const uint32_t sB = sA + STAGES * ABYTES;

    const int t   = threadIdx.x;
    const int wid = t >> 5, lid = t & 31;
    const int wm  = wid >> 2;
    const int wn  = wid & 3;
    const long lda = 2L * Khalf;
    const int m0 = blockIdx.y * BM, n0 = blockIdx.x * 128;

    A += (long)m0 * lda;
    B += (long)n0 * lda;

    const int a_row = (lid & 7) + ((lid >> 3) & 1) * 8;
    const int a_c8  = (lid >> 4) * 8;
    const int lb    = lid & 15;
    const int b_row = lb & 7;
    const int b_c8  = ((lb >> 3) & 1) * 8;
    const uint32_t aBase = sA + ((wm * (BM / 2) + a_row) * APAD + a_c8) * 2;
    const uint32_t bBase = sB + ((wn * 32 + b_row) * APAD + b_c8) * 2;

    const int nk  = Khalf >> 5;
    const int nk3 = 3 * nk;

    float acc[MI][4][4];
#pragma unroll
    for (int i = 0; i < MI; i++)
#pragma unroll
        for (int j = 0; j < 4; j++)
#pragma unroll
            for (int r = 0; r < 4; r++) acc[i][j][r] = 0.0f;

    auto issue = [&](int c) {
        int r  = c / nk;
        int kk = c - r * nk;
        long ao = (long)((r == 1) ? Khalf : 0) + (long)kk * 32;
        long bo = (long)((r == 2) ? Khalf : 0) + (long)kk * 32;
        uint32_t stA = (uint32_t)(c & (STAGES - 1)) * ABYTES;
        uint32_t stB = (uint32_t)(c & (STAGES - 1)) * BBYTES;
#pragma unroll
        for (int i = 0; i < ACP; i++) {
            int idx = t + i * 256, row = idx >> 2, q = (idx & 3) * 8;
            cp16(sA + stA + (row * APAD + q) * 2, A + (long)row * lda + ao + q);
        }
#pragma unroll
        for (int i = 0; i < 2; i++) {
            int idx = t + i * 256, row = idx >> 2, q = (idx & 3) * 8;
            cp16(sB + stB + (row * APAD + q) * 2, B + (long)row * lda + bo + q);
        }
    };

#pragma unroll
    for (int s = 0; s < STAGES - 1; s++) {
        issue(s);
        asm volatile("cp.async.commit_group;" ::: "memory");
    }

    for (int c = 0; c < nk3; c++) {
        asm volatile("cp.async.wait_group %0;" :: "n"(STAGES - 2) : "memory");
        __syncthreads();

        const uint32_t stA = (uint32_t)(c & (STAGES - 1)) * ABYTES;
        const uint32_t stB = (uint32_t)(c & (STAGES - 1)) * BBYTES;
#pragma unroll
        for (int ks = 0; ks < 2; ks++) {
            uint32_t af[MI][4], bf[4][2];
#pragma unroll
            for (int mi = 0; mi < MI; mi++)
                ldx4(af[mi], aBase + stA + (mi * 16 * APAD + ks * 16) * 2);
#pragma unroll
            for (int nj = 0; nj < 4; nj++)
                ldx2(bf[nj], bBase + stB + (nj * 8 * APAD + ks * 16) * 2);
#pragma unroll
            for (int mi = 0; mi < MI; mi++)
#pragma unroll
                for (int nj = 0; nj < 4; nj++)
                    hmma(acc[mi][nj], af[mi], bf[nj]);
        }
        if (c + STAGES - 1 < nk3) issue(c + STAGES - 1);
        asm volatile("cp.async.commit_group;" ::: "memory");
    }

    const int er = lid >> 2;
    const int ec = (lid & 3) * 2;
#pragma unroll
    for (int nj = 0; nj < 4; nj++) {
        int col = n0 + wn * 32 + nj * 8 + ec;
        float b0 = 0.f, b1 = 0.f;
        if (bias) { b0 = __ldg(bias + col); b1 = __ldg(bias + col + 1); }
#pragma unroll
        for (int mi = 0; mi < MI; mi++) {
            int row0 = m0 + wm * (BM / 2) + mi * 16 + er;
            float2 v0 = { alpha * acc[mi][nj][0] + b0, alpha * acc[mi][nj][1] + b1 };
            float2 v1 = { alpha * acc[mi][nj][2] + b0, alpha * acc[mi][nj][3] + b1 };
            *(float2*)(C + (long)row0 * ldc + col)       = v0;
            *(float2*)(C + (long)(row0 + 8) * ldc + col) = v1;
        }
    }
}

// ------------------------- fused flash attention -----------------------------
// grid (TT/128, NHQ), 256 thr, occ 1. Per warp: 16 q rows x full 128-key chunk.
// S = 3-term split QK^T, online softmax (exp2), P split in-register, O += 3-term P@V.
#define KPAD 264
#define VPAD 136
#define FSM_BYTES ((128 * KPAD * 2 + 128 * VPAD * 2) * 2)   // 204800

__global__ __launch_bounds__(256, 1) void flash_attn(
    const __nv_bfloat16* __restrict__ Qe,
    const __nv_bfloat16* __restrict__ Ke,
    const __nv_bfloat16* __restrict__ Ve,
    __nv_bfloat16* __restrict__ Oex)
{
    extern __shared__ char fsm[];
    const uint32_t uQ  = smem_u32(fsm);
    const uint32_t uK  = uQ + 128 * KPAD * 2;
    const uint32_t uVh = uK + 128 * KPAD * 2;
    const uint32_t uVl = uVh + 128 * VPAD * 2;

    const int t = threadIdx.x, wid = t >> 5, lid = t & 31;
    const int h = blockIdx.y, hk = h / GQA;
    const int q0 = blockIdx.x * 128;

    const __nv_bfloat16* Qg = Qe + ((long)h * TT + q0) * 256;
    const __nv_bfloat16* Kg = Ke + (long)hk * TT * 256;
    const __nv_bfloat16* Vg = Ve + (long)hk * HDIM * (2 * TT);

    auto loadK = [&](int kc) {
        const __nv_bfloat16* src = Kg + (long)kc * 128 * 256;
#pragma unroll
        for (int i = 0; i < 16; i++) {
            int idx = t + i * 256, row = idx >> 5, ce = (idx & 31) * 8;
            cp16(uK + (row * KPAD + ce) * 2, src + (long)row * 256 + ce);
        }
    };
    auto loadV = [&](int kc) {
#pragma unroll
        for (int i = 0; i < 8; i++) {
            int idx = t + i * 256, row = idx >> 4, ce = (idx & 15) * 8;
            const __nv_bfloat16* s = Vg + (long)row * (2 * TT) + kc * 128 + ce;
            cp16(uVh + (row * VPAD + ce) * 2, s);
            cp16(uVl + (row * VPAD + ce) * 2, s + TT);
        }
    };

    // prologue loads: Q, K0, V0
#pragma unroll
    for (int i = 0; i < 16; i++) {
        int idx = t + i * 256, row = idx >> 5, ce = (idx & 31) * 8;
        cp16(uQ + (row * KPAD + ce) * 2, Qg + (long)row * 256 + ce);
    }
    loadK(0);
    loadV(0);
    asm volatile("cp.async.commit_group;" ::: "memory");
    asm volatile("cp.async.wait_group 0;" ::: "memory");
    __syncthreads();

    const int a_row = (lid & 7) + ((lid >> 3) & 1) * 8;
    const int a_c8  = (lid >> 4) * 8;
    const int lb    = lid & 15;
    const int b_row = lb & 7;
    const int b_c8  = ((lb >> 3) & 1) * 8;
    const uint32_t aQbase = uQ + ((wid * 16 + a_row) * KPAD + a_c8) * 2;

    float oacc[16][4];
#pragma unroll
    for (int nj = 0; nj < 16; nj++)
#pragma unroll
        for (int r = 0; r < 4; r++) oacc[nj][r] = 0.0f;
    float m0 = -1e30f, m1 = -1e30f, l0 = 0.0f, l1 = 0.0f;

    for (int kc = 0; kc < TT / 128; kc++) {
        // ---- S = scale*log2e * Q@K^T (3-term split) ----
        float sacc[16][4];
#pragma unroll
        for (int nj = 0; nj < 16; nj++)
#pragma unroll
            for (int r = 0; r < 4; r++) sacc[nj][r] = 0.0f;

#pragma unroll
        for (int ks = 0; ks < 8; ks++) {
            uint32_t aqh[4], aql[4];
            ldx4(aqh, aQbase + (ks * 16) * 2);
            ldx4(aql, aQbase + (128 + ks * 16) * 2);
#pragma unroll
            for (int nj = 0; nj < 16; nj++) {
                uint32_t bk[2];
                ldx2(bk, uK + ((nj * 8 + b_row) * KPAD + ks * 16 + b_c8) * 2);
                hmma(sacc[nj], aqh, bk);          // Qhi * Khi
                hmma(sacc[nj], aql, bk);          // Qlo * Khi
                ldx2(bk, uK + ((nj * 8 + b_row) * KPAD + 128 + ks * 16 + b_c8) * 2);
                hmma(sacc[nj], aqh, bk);          // Qhi * Klo
            }
        }
        __syncthreads();                            // done reading sK
        if (kc + 1 < TT / 128) loadK(kc + 1);
        asm volatile("cp.async.commit_group;" ::: "memory");

        // ---- online softmax (rows fully owned: shfl over 4 lanes) ----
        float mx0 = -1e30f, mx1 = -1e30f;
#pragma unroll
        for (int nj = 0; nj < 16; nj++) {
            sacc[nj][0] *= SCALE_L2E; sacc[nj][1] *= SCALE_L2E;
            sacc[nj][2] *= SCALE_L2E; sacc[nj][3] *= SCALE_L2E;
            mx0 = fmaxf(mx0, fmaxf(sacc[nj][0], sacc[nj][1]));
            mx1 = fmaxf(mx1, fmaxf(sacc[nj][2], sacc[nj][3]));
        }
        mx0 = fmaxf(mx0, __shfl_xor_sync(0xffffffffu, mx0, 1));
        mx0 = fmaxf(mx0, __shfl_xor_sync(0xffffffffu, mx0, 2));
        mx1 = fmaxf(mx1, __shfl_xor_sync(0xffffffffu, mx1, 1));
        mx1 = fmaxf(mx1, __shfl_xor_sync(0xffffffffu, mx1, 2));
        float nm0 = fmaxf(m0, mx0), nm1 = fmaxf(m1, mx1);
        float sc0 = exp2f(m0 - nm0), sc1 = exp2f(m1 - nm1);
        m0 = nm0; m1 = nm1;
        l0 *= sc0; l1 *= sc1;
#pragma unroll
        for (int nj = 0; nj < 16; nj++) {
            oacc[nj][0] *= sc0; oacc[nj][1] *= sc0;
            oacc[nj][2] *= sc1; oacc[nj][3] *= sc1;
            sacc[nj][0] = exp2f(sacc[nj][0] - m0);
            sacc[nj][1] = exp2f(sacc[nj][1] - m0);
            sacc[nj][2] = exp2f(sacc[nj][2] - m1);
            sacc[nj][3] = exp2f(sacc[nj][3] - m1);
            l0 += sacc[nj][0] + sacc[nj][1];
            l1 += sacc[nj][2] + sacc[nj][3];
        }

        // ---- O += P @ V (3-term split; P frags from S C-frags) ----
#pragma unroll
        for (int ks = 0; ks < 8; ks++) {
            uint32_t ph[4], pl[4];
            packsplit(sacc[2 * ks][0],     sacc[2 * ks][1],     ph[0], pl[0]);
            packsplit(sacc[2 * ks][2],     sacc[2 * ks][3],     ph[1], pl[1]);
            packsplit(sacc[2 * ks + 1][0], sacc[2 * ks + 1][1], ph[2], pl[2]);
            packsplit(sacc[2 * ks + 1][2], sacc[2 * ks + 1][3], ph[3], pl[3]);
#pragma unroll
            for (int nj = 0; nj < 16; nj++) {
                uint32_t bv[2];
                ldx2(bv, uVh + ((nj * 8 + b_row) * VPAD + ks * 16 + b_c8) * 2);
                hmma(oacc[nj], ph, bv);           // Phi * Vhi
                hmma(oacc[nj], pl, bv);           // Plo * Vhi
                ldx2(bv, uVl + ((nj * 8 + b_row) * VPAD + ks * 16 + b_c8) * 2);
                hmma(oacc[nj], ph, bv);           // Phi * Vlo
            }
        }
        __syncthreads();                            // done reading sV
        if (kc + 1 < TT / 128) {
            loadV(kc + 1);
            asm volatile("cp.async.commit_group;" ::: "memory");
            asm volatile("cp.async.wait_group 0;" ::: "memory");
        }
        __syncthreads();
    }

    // ---- epilogue: normalize, split, write attnex ----
    l0 += __shfl_xor_sync(0xffffffffu, l0, 1);
    l0 += __shfl_xor_sync(0xffffffffu, l0, 2);
    l1 += __shfl_xor_sync(0xffffffffu, l1, 1);
    l1 += __shfl_xor_sync(0xffffffffu, l1, 2);
    const float inv0 = 1.0f / l0, inv1 = 1.0f / l1;

    const int gr = lid >> 2;
    const int ec = (lid & 3) * 2;
    const long r0 = q0 + wid * 16 + gr;
    const long r1 = r0 + 8;
#pragma unroll
    for (int nj = 0; nj < 16; nj++) {
        int col = h * HDIM + nj * 8 + ec;
        uint32_t hi, lo;
        packsplit(oacc[nj][0] * inv0, oacc[nj][1] * inv0, hi, lo);
        *(uint32_t*)(Oex + r0 * (2 * HIDD) + col)        = hi;
        *(uint32_t*)(Oex + r0 * (2 * HIDD) + HIDD + col) = lo;
        packsplit(oacc[nj][2] * inv1, oacc[nj][3] * inv1, hi, lo);
        *(uint32_t*)(Oex + r1 * (2 * HIDD) + col)        = hi;
        *(uint32_t*)(Oex + r1 * (2 * HIDD) + HIDD + col) = lo;
    }
}

// ------------------------- conversion kernels -------------------------------
__global__ void split_rows(const float* __restrict__ in, __nv_bfloat16* __restrict__ out,
                           int K, long total4)
{
    long i = (long)blockIdx.x * blockDim.x + threadIdx.x;
    if (i >= total4) return;
    long e = i * 4;
    long r = e / K;
    int  k = (int)(e - r * K);
    float4 x = *(const float4*)(in + e);
    __nv_bfloat16 h0,l0,h1,l1,h2,l2,h3,l3;
    split2(x.x,h0,l0); split2(x.y,h1,l1); split2(x.z,h2,l2); split2(x.w,h3,l3);
    __nv_bfloat16* oh = out + r * 2L * K + k;
    oh[0]=h0; oh[1]=h1; oh[2]=h2; oh[3]=h3;
    __nv_bfloat16* ol = oh + K;
    ol[0]=l0; ol[1]=l1; ol[2]=l2; ol[3]=l3;
}

__global__ void split_transpose(const float* __restrict__ in, int ldin, long inBatch,
                                __nv_bfloat16* __restrict__ out, int Kdim, long outBatch)
{
    __shared__ float smt[32][33];
    const float* ip = in + (long)blockIdx.z * inBatch;
    __nv_bfloat16* op = out + (long)blockIdx.z * outBatch;
    int k0 = blockIdx.x * 32, n0 = blockIdx.y * 32;
    int tx = threadIdx.x, ty = threadIdx.y;
    for (int i = ty; i < 32; i += 8) smt[i][tx] = ip[(long)(k0 + i) * ldin + n0 + tx];
    __syncthreads();
    for (int j = ty; j < 32; j += 8) {
        float x = smt[tx][j];
        __nv_bfloat16 h, l; split2(x, h, l);
        long ob = (long)(n0 + j) * (2L * Kdim) + k0 + tx;
        op[ob] = h; op[ob + Kdim] = l;
    }
}

__global__ void rope_split(const float* __restrict__ x, int ld, const int* __restrict__ pos,
                           __nv_bfloat16* __restrict__ out)
{
    int t = blockIdx.x, h = blockIdx.y, d = threadIdx.x; // d in [0,64)
    const float* row = x + (long)t * ld + h * HDIM;
    float p = (float)pos[t];
    float ang = p * exp2f(-(float)d * (LOG2_THETA / 64.0f));
    float s, c;
    sincosf(ang, &s, &c);
    float x1 = row[d], x2 = row[d + 64];
    float y1 = x1 * c - x2 * s;
    float y2 = x2 * c + x1 * s;
    __nv_bfloat16 h1, l1, h2, l2;
    split2(y1, h1, l1); split2(y2, h2, l2);
    __nv_bfloat16* o = out + ((long)h * TT + t) * (2 * HDIM);
    o[d] = h1; o[d + 64] = h2;
    o[128 + d] = l1; o[128 + d + 64] = l2;
}

__global__ void concat_bias(const float* __restrict__ bq, const float* __restrict__ bk,
                            const float* __restrict__ bv, float* __restrict__ o)
{
    int i = blockIdx.x * 256 + threadIdx.x;
    if (i >= NQKV) return;
    if (i < HIDD)            o[i] = bq[i];
    else if (i < HIDD + 512) o[i] = bk[i - HIDD];
    else                     o[i] = bv[i - HIDD - 512];
}

// ------------------------- launch -------------------------------------------
extern "C" void kernel_launch(void* const* d_in, const int* in_sizes, int n_in,
                              void* d_out, int out_size)
{
    const int*   pos = (const int*)d_in[0];
    const float* hs  = (const float*)d_in[1];
    const float* wq  = (const float*)d_in[2];
    const float* bq  = (const float*)d_in[3];
    const float* wk  = (const float*)d_in[4];
    const float* bk  = (const float*)d_in[5];
    const float* wv  = (const float*)d_in[6];
    const float* bv  = (const float*)d_in[7];
    const float* wo  = (const float*)d_in[8];
    float* out = (float*)d_out;

    __nv_bfloat16 *hsex, *wqkvex, *woex, *qex, *kex, *vex, *attnex;
    float *qkv, *bqkv;
    cudaGetSymbolAddress((void**)&hsex,   g_hsex);
    cudaGetSymbolAddress((void**)&wqkvex, g_wqkvex);
    cudaGetSymbolAddress((void**)&bqkv,   g_bqkv);
    cudaGetSymbolAddress((void**)&woex,   g_woex);
    cudaGetSymbolAddress((void**)&qkv,    g_qkv);
    cudaGetSymbolAddress((void**)&qex,    g_qex);
    cudaGetSymbolAddress((void**)&kex,    g_kex);
    cudaGetSymbolAddress((void**)&vex,    g_vex);
    cudaGetSymbolAddress((void**)&attnex, g_attnex);

    static bool attrDone = false;
    if (!attrDone) {
        cudaFuncSetAttribute(mma_gemm<128>, cudaFuncAttributeMaxDynamicSharedMemorySize,
                             STAGES * (128 + 128) * APAD * 2);
        cudaFuncSetAttribute(flash_attn, cudaFuncAttributeMaxDynamicSharedMemorySize,
                             FSM_BYTES);
        attrDone = true;
    }
    const int smem128 = STAGES * (128 + 128) * APAD * 2;

    // ---- operand conversions ----
    {
        long t4 = (long)TT * HIDD / 4;
        split_rows<<<(unsigned)((t4 + 255) / 256), 256>>>(hs, hsex, HIDD, t4);
    }
    split_transpose<<<dim3(HIDD/32, HIDD/32, 1), dim3(32,8)>>>(wq, HIDD, 0, wqkvex, HIDD, 0);
    split_transpose<<<dim3(HIDD/32, 512/32, 1), dim3(32,8)>>>(wk, 512, 0,
        wqkvex + (size_t)HIDD * 2 * HIDD, HIDD, 0);
    split_transpose<<<dim3(HIDD/32, 512/32, 1), dim3(32,8)>>>(wv, 512, 0,
        wqkvex + (size_t)(HIDD + 512) * 2 * HIDD, HIDD, 0);
    split_transpose<<<dim3(HIDD/32, HIDD/32, 1), dim3(32,8)>>>(wo, HIDD, 0, woex, HIDD, 0);
    concat_bias<<<(NQKV + 255) / 256, 256>>>(bq, bk, bv, bqkv);

    // ---- fused QKV projection ----
    mma_gemm<128><<<dim3(NQKV/128, TT/128, 1), 256, smem128>>>(
        hsex, wqkvex, bqkv, qkv, NQKV, HIDD, 1.0f);

    // ---- RoPE + split; V transpose + split ----
    rope_split<<<dim3(TT, NHQ), 64>>>(qkv, NQKV, pos, qex);
    rope_split<<<dim3(TT, NKVH), 64>>>(qkv + HIDD, NQKV, pos, kex);
    split_transpose<<<dim3(TT/32, HDIM/32, NKVH), dim3(32,8)>>>(
        qkv + HIDD + 512, NQKV, (long)HDIM, vex, TT, (long)HDIM * 2 * TT);

    // ---- fused attention: QK^T + softmax + PV -> attnex (split) ----
    flash_attn<<<dim3(TT/128, NHQ), 256, FSM_BYTES>>>(qex, kex, vex, attnex);

    // ---- out = attn @ wo ----
    mma_gemm<128><<<dim3(HIDD/128, TT/128, 1), 256, smem128>>>(
        attnex, woex, nullptr, out, HIDD, HIDD, 1.0f);
}